// round 4
// baseline (speedup 1.0000x reference)
#include <cuda_runtime.h>
#include <cuda_bf16.h>

// NnInteractionTokenizer: bond = x[row]*x[col]; local_field = segsum(bond, row);
// tokens = relu(relu([x, lf] @ w1^T + b1) @ w2^T + b2)
//
// Algebraic simplification: local_field[r] = x[r] * sum_{e: row[e]=r} x[col[e]]
// -> edge phase only accumulates x[col[e]] into g_acc[row[e]] (one gather, one
//    float REDG per edge); the x[r] multiply folds into the node phase.

#define N_NODES 100000
#define N_EDGES 6400000
#define TD 16
#define EPT 8    // edges per thread (edge kernel)
#define NPT 2    // nodes per thread (node kernel)
#define NTB 256  // node kernel block size

// Scratch (no device allocation allowed -> __device__ globals)
__device__ float g_acc[N_NODES];
__device__ int   g_is64;

// ---------------------------------------------------------------------------
// Init: zero the accumulator; block 0 additionally probes edge_index dtype.
// The reference asks for int64, but JAX without x64 silently yields int32.
// As uint32 words, int64 data (values < 2^17, LE) has all odd words == 0;
// int32 data has random values in [0, 100000) -> P(256 zero odd-words) ~ 0.
// ---------------------------------------------------------------------------
__global__ void __launch_bounds__(256) init_kernel(const unsigned int* __restrict__ w) {
    const int i = blockIdx.x * 256 + threadIdx.x;
    if (i < N_NODES) g_acc[i] = 0.0f;

    if (blockIdx.x == 0) {
        __shared__ int nz;
        if (threadIdx.x == 0) nz = 0;
        __syncthreads();
        if (w[threadIdx.x * 2 + 1] != 0u) atomicAdd(&nz, 1);
        __syncthreads();
        if (threadIdx.x == 0) g_is64 = (nz == 0) ? 1 : 0;
    }
}

// ---------------------------------------------------------------------------
// Edge phase: EPT edges per thread, vectorized index loads (DRAM-streaming),
// batched gathers (MLP=EPT, L2/L1-resident x) then EPT REDG.F32 into g_acc.
// This kernel sits at the LTS throughput cap — do not add work here.
// ---------------------------------------------------------------------------
__global__ void __launch_bounds__(256) edge_kernel(const void* __restrict__ ei,
                                                   const float* __restrict__ x) {
    const int tid = blockIdx.x * blockDim.x + threadIdx.x;
    const long long base = (long long)tid * EPT;
    if (base >= N_EDGES) return;

    int r[EPT], c[EPT];
    if (g_is64) {
        const longlong2* row = (const longlong2*)ei;          // edge_index[0]
        const longlong2* col = row + (N_EDGES / 2);           // edge_index[1]
#pragma unroll
        for (int k = 0; k < EPT / 2; k++) {
            longlong2 rv = __ldg(&row[base / 2 + k]);
            r[2 * k] = (int)rv.x; r[2 * k + 1] = (int)rv.y;
        }
#pragma unroll
        for (int k = 0; k < EPT / 2; k++) {
            longlong2 cv = __ldg(&col[base / 2 + k]);
            c[2 * k] = (int)cv.x; c[2 * k + 1] = (int)cv.y;
        }
    } else {
        const int4* row = (const int4*)ei;
        const int4* col = row + (N_EDGES / 4);
#pragma unroll
        for (int k = 0; k < EPT / 4; k++) {
            int4 rv = __ldg(&row[base / 4 + k]);
            r[4 * k] = rv.x; r[4 * k + 1] = rv.y; r[4 * k + 2] = rv.z; r[4 * k + 3] = rv.w;
        }
#pragma unroll
        for (int k = 0; k < EPT / 4; k++) {
            int4 cv = __ldg(&col[base / 4 + k]);
            c[4 * k] = cv.x; c[4 * k + 1] = cv.y; c[4 * k + 2] = cv.z; c[4 * k + 3] = cv.w;
        }
    }

    float v[EPT];
#pragma unroll
    for (int k = 0; k < EPT; k++) v[k] = __ldg(&x[c[k]]);
#pragma unroll
    for (int k = 0; k < EPT; k++) atomicAdd(&g_acc[r[k]], v[k]);
}

// ---------------------------------------------------------------------------
// Node phase: per-node 2->16->16 MLP. NPT=2 nodes per thread so every sw2
// shared-load (float4 -> LDS.128) amortizes over 2 nodes x 4 weights:
// 32 LDS/node instead of 256 scalar LDS/node. Output via STG.128.
// ---------------------------------------------------------------------------
__global__ void __launch_bounds__(NTB) node_kernel(const float* __restrict__ x,
                                                   const float* __restrict__ w1,
                                                   const float* __restrict__ b1,
                                                   const float* __restrict__ w2,
                                                   const float* __restrict__ b2,
                                                   float* __restrict__ out) {
    __shared__ float sw1[2 * TD];
    __shared__ float sb1[TD];
    __shared__ __align__(16) float sw2[TD * TD];
    __shared__ float sb2[TD];

    const int t = threadIdx.x;
    if (t < 2 * TD) sw1[t] = w1[t];
    if (t < TD) { sb1[t] = b1[t]; sb2[t] = b2[t]; }
    for (int i = t; i < TD * TD; i += NTB) sw2[i] = w2[i];
    __syncthreads();

    const int n0 = blockIdx.x * (NTB * NPT) + t;   // node for slot 0
    const int n1 = n0 + NTB;                        // node for slot 1
    const bool a0 = (n0 < N_NODES);
    const bool a1 = (n1 < N_NODES);

    // Issue the 4 global loads up front (MLP=4, L2-resident).
    float s0 = 0.f, s1 = 0.f, lf0 = 0.f, lf1 = 0.f;
    if (a0) { s0 = x[n0]; lf0 = g_acc[n0]; }
    if (a1) { s1 = x[n1]; lf1 = g_acc[n1]; }
    lf0 *= s0;
    lf1 *= s1;

    // Layer 1: h = relu(s*w1[:,0] + lf*w1[:,1] + b1)
    float h0[TD], h1[TD];
#pragma unroll
    for (int j = 0; j < TD; j++) {
        const float wa = sw1[2 * j], wb = sw1[2 * j + 1], bb = sb1[j];
        float v0 = fmaf(wb, lf0, fmaf(wa, s0, bb));
        float v1 = fmaf(wb, lf1, fmaf(wa, s1, bb));
        h0[j] = v0 > 0.f ? v0 : 0.f;
        h1[j] = v1 > 0.f ? v1 : 0.f;
    }

    // Layer 2: tokens = relu(W2 h + b2); weights read as LDS.128, reused 2x.
    float4* o0 = (float4*)(out + (size_t)n0 * TD);
    float4* o1 = (float4*)(out + (size_t)n1 * TD);
#pragma unroll
    for (int k4 = 0; k4 < 4; k4++) {
        float4 res0, res1;
        float* rp0 = (float*)&res0;
        float* rp1 = (float*)&res1;
#pragma unroll
        for (int kk = 0; kk < 4; kk++) {
            const int k = k4 * 4 + kk;
            float v0 = sb2[k], v1 = v0;
            const float4* wrow = (const float4*)&sw2[k * TD];
#pragma unroll
            for (int j4 = 0; j4 < 4; j4++) {
                float4 w = wrow[j4];
                v0 = fmaf(w.x, h0[j4 * 4 + 0], v0);
                v1 = fmaf(w.x, h1[j4 * 4 + 0], v1);
                v0 = fmaf(w.y, h0[j4 * 4 + 1], v0);
                v1 = fmaf(w.y, h1[j4 * 4 + 1], v1);
                v0 = fmaf(w.z, h0[j4 * 4 + 2], v0);
                v1 = fmaf(w.z, h1[j4 * 4 + 2], v1);
                v0 = fmaf(w.w, h0[j4 * 4 + 3], v0);
                v1 = fmaf(w.w, h1[j4 * 4 + 3], v1);
            }
            rp0[kk] = v0 > 0.f ? v0 : 0.f;
            rp1[kk] = v1 > 0.f ? v1 : 0.f;
        }
        if (a0) o0[k4] = res0;
        if (a1) o1[k4] = res1;
    }
}

extern "C" void kernel_launch(void* const* d_in, const int* in_sizes, int n_in,
                              void* d_out, int out_size) {
    const float* x  = (const float*)d_in[0];
    const void*  ei = d_in[1];
    const float* w1 = (const float*)d_in[2];
    const float* b1 = (const float*)d_in[3];
    const float* w2 = (const float*)d_in[4];
    const float* b2 = (const float*)d_in[5];
    float* out = (float*)d_out;

    init_kernel<<<(N_NODES + 255) / 256, 256>>>((const unsigned int*)ei);
    edge_kernel<<<N_EDGES / EPT / 256, 256>>>(ei, x);
    node_kernel<<<(N_NODES + NTB * NPT - 1) / (NTB * NPT), NTB>>>(x, w1, b1, w2, b2, out);
}

// round 6
// speedup vs baseline: 1.0592x; 1.0592x over previous
#include <cuda_runtime.h>
#include <cuda_bf16.h>

// NnInteractionTokenizer: bond = x[row]*x[col]; local_field = segsum(bond, row);
// tokens = relu(relu([x, lf] @ w1^T + b1) @ w2^T + b2)
//
// Algebraic simplification: local_field[r] = x[r] * sum_{e: row[e]=r} x[col[e]]
// -> edge phase only accumulates x[col[e]] into g_acc[row[e]] (one gather, one
//    float REDG per edge); the x[r] multiply folds into the node phase.
//
// No init kernel: __device__ globals start zeroed; node_kernel re-zeroes
// g_acc after consuming it, so g_acc == 0 at entry of every kernel_launch
// (correctness call, and every graph replay). Deterministic.

#define N_NODES 100000
#define N_EDGES 6400000
#define TD 16
#define EPT 4    // edges per thread (edge kernel) — EPT=8 regressed (L1tex-queue spread)
#define TPN 4    // threads per node (node kernel)

// Scratch (no device allocation allowed -> __device__ globals; zero-initialized)
__device__ float g_acc[N_NODES];

// ---------------------------------------------------------------------------
// Edge phase: EPT edges per thread, vectorized index loads (DRAM-streaming),
// batched gathers (L2/L1-resident x) then EPT REDG.F32 into g_acc.
//
// Dtype probe (per block, uniform): the reference asks for int64, but JAX
// without x64 silently yields int32. As uint32 words, int64 data (values
// < 2^17, LE) has odd words == 0; int32 data has random values in
// [0, 100000) -> P(8 specific odd words all zero) ~ 1e-40. Every block reads
// the SAME 8 words (L2 broadcast) so the decision is globally uniform.
// ---------------------------------------------------------------------------
__global__ void __launch_bounds__(256) edge_kernel(const void* __restrict__ ei,
                                                   const float* __restrict__ x) {
    __shared__ int s_is64;
    if (threadIdx.x == 0) {
        const unsigned int* w = (const unsigned int*)ei;
        unsigned int acc = 0;
#pragma unroll
        for (int k = 0; k < 8; k++) acc |= w[2 * k + 1];
        s_is64 = (acc == 0u) ? 1 : 0;
    }
    __syncthreads();

    const int tid = blockIdx.x * blockDim.x + threadIdx.x;
    const long long base = (long long)tid * EPT;
    if (base >= N_EDGES) return;

    int r[EPT], c[EPT];
    if (s_is64) {
        const longlong2* row = (const longlong2*)ei;          // edge_index[0]
        const longlong2* col = row + (N_EDGES / 2);           // edge_index[1]
        longlong2 r0 = __ldg(&row[base / 2]);
        longlong2 r1 = __ldg(&row[base / 2 + 1]);
        longlong2 c0 = __ldg(&col[base / 2]);
        longlong2 c1 = __ldg(&col[base / 2 + 1]);
        r[0] = (int)r0.x; r[1] = (int)r0.y; r[2] = (int)r1.x; r[3] = (int)r1.y;
        c[0] = (int)c0.x; c[1] = (int)c0.y; c[2] = (int)c1.x; c[3] = (int)c1.y;
    } else {
        const int4* row = (const int4*)ei;
        const int4* col = row + (N_EDGES / 4);
        int4 rv = __ldg(&row[base / 4]);
        int4 cv = __ldg(&col[base / 4]);
        r[0] = rv.x; r[1] = rv.y; r[2] = rv.z; r[3] = rv.w;
        c[0] = cv.x; c[1] = cv.y; c[2] = cv.z; c[3] = cv.w;
    }

    float v[EPT];
#pragma unroll
    for (int k = 0; k < EPT; k++) v[k] = __ldg(&x[c[k]]);
#pragma unroll
    for (int k = 0; k < EPT; k++) atomicAdd(&g_acc[r[k]], v[k]);
}

// ---------------------------------------------------------------------------
// Node phase: 2->16->16 MLP, TPN=4 threads per node. Layer 1 (32 FMA) is
// recomputed by all 4 threads (cheap); layer 2 is split 4 outputs/thread.
// 400K threads lifts the occupancy ceiling 4x vs 1-thread-per-node (which
// measured 9.3us at 29.6% occ / 25.5% issue). Stores are coalesced STG.128.
// Also re-zeroes g_acc (after the block barrier) for the next graph replay.
// The single __syncthreads orders BOTH the smem weight publish and the
// g_acc read-before-clear (all 4 readers of node n are in the same block).
// ---------------------------------------------------------------------------
__global__ void __launch_bounds__(256) node_kernel(const float* __restrict__ x,
                                                   const float* __restrict__ w1,
                                                   const float* __restrict__ b1,
                                                   const float* __restrict__ w2,
                                                   const float* __restrict__ b2,
                                                   float* __restrict__ out) {
    __shared__ float sw1[2 * TD];
    __shared__ float sb1[TD];
    __shared__ __align__(16) float sw2[TD * TD];
    __shared__ float sb2[TD];

    const int t = threadIdx.x;
    if (t < 2 * TD) sw1[t] = w1[t];
    if (t < TD) { sb1[t] = b1[t]; sb2[t] = b2[t]; }
    if (t < TD * TD) sw2[t] = w2[t];

    const int g  = blockIdx.x * 256 + t;
    const int n  = g >> 2;        // node index
    const int kq = g & 3;         // output quarter (4 outputs of 16)
    const bool act = (n < N_NODES);

    // Read inputs before the barrier; zero g_acc after it.
    float s = 0.f, lfa = 0.f;
    if (act) { s = x[n]; lfa = g_acc[n]; }
    __syncthreads();
    if (act && kq == 0) g_acc[n] = 0.0f;

    const float lf = s * lfa;

    // Layer 1: h = relu(s*w1[:,0] + lf*w1[:,1] + b1)   (broadcast LDS)
    float h[TD];
#pragma unroll
    for (int j = 0; j < TD; j++) {
        float v = fmaf(sw1[2 * j + 1], lf, fmaf(sw1[2 * j], s, sb1[j]));
        h[j] = v > 0.f ? v : 0.f;
    }

    // Layer 2: this thread's 4 outputs k = kq*4 .. kq*4+3  (LDS.128 weights)
    float4 res;
    float* rp = (float*)&res;
#pragma unroll
    for (int kk = 0; kk < 4; kk++) {
        const int k = kq * 4 + kk;
        float v = sb2[k];
        const float4* wrow = (const float4*)&sw2[k * TD];
#pragma unroll
        for (int j4 = 0; j4 < 4; j4++) {
            float4 w = wrow[j4];
            v = fmaf(w.x, h[j4 * 4 + 0], v);
            v = fmaf(w.y, h[j4 * 4 + 1], v);
            v = fmaf(w.z, h[j4 * 4 + 2], v);
            v = fmaf(w.w, h[j4 * 4 + 3], v);
        }
        rp[kk] = v > 0.f ? v : 0.f;
    }
    if (act) ((float4*)(out + (size_t)n * TD))[kq] = res;
}

extern "C" void kernel_launch(void* const* d_in, const int* in_sizes, int n_in,
                              void* d_out, int out_size) {
    const float* x  = (const float*)d_in[0];
    const void*  ei = d_in[1];
    const float* w1 = (const float*)d_in[2];
    const float* b1 = (const float*)d_in[3];
    const float* w2 = (const float*)d_in[4];
    const float* b2 = (const float*)d_in[5];
    float* out = (float*)d_out;

    edge_kernel<<<N_EDGES / EPT / 256, 256>>>(ei, x);
    node_kernel<<<(N_NODES * TPN + 255) / 256, 256>>>(x, w1, b1, w2, b2, out);
}

// round 7
// speedup vs baseline: 1.1535x; 1.0890x over previous
#include <cuda_runtime.h>
#include <cuda_bf16.h>

// NnInteractionTokenizer: bond = x[row]*x[col]; local_field = segsum(bond, row);
// tokens = relu(relu([x, lf] @ w1^T + b1) @ w2^T + b2)
//
// Algebraic simplification: local_field[r] = x[r] * sum_{e: row[e]=r} x[col[e]]
// -> edge phase only accumulates x[col[e]] into g_acc[row[e]] (one gather, one
//    float REDG per edge); the x[r] multiply folds into the node phase.
//
// No init kernel: __device__ globals start zeroed; in node_kernel the SAME
// thread that reads g_acc[n] writes 0 back (same-thread same-address order,
// no barrier), so g_acc == 0 at entry of every kernel_launch / graph replay.

#define N_NODES 100000
#define N_EDGES 6400000
#define TD 16
#define EPT 4    // edges per thread — EPT=8 regressed (L1tex-queue spread)

// Scratch (no device allocation allowed -> __device__ globals; zero-initialized)
__device__ float g_acc[N_NODES];

// ---------------------------------------------------------------------------
// Edge phase (UNCHANGED from R6 — measured ~52us, at the LTS throughput cap):
// EPT edges per thread, vectorized index loads (DRAM-streaming), batched
// gathers (L1/L2-resident x) then EPT REDG.F32 into g_acc.
//
// Dtype probe (per block, uniform): the reference asks for int64, but JAX
// without x64 silently yields int32. As uint32 words, int64 data (values
// < 2^17, LE) has odd words == 0; int32 data has random values in
// [0, 100000) -> P(8 specific odd words all zero) ~ 1e-40. Every block reads
// the SAME 8 words (L2 broadcast) so the decision is globally uniform.
// ---------------------------------------------------------------------------
__global__ void __launch_bounds__(256) edge_kernel(const void* __restrict__ ei,
                                                   const float* __restrict__ x) {
    __shared__ int s_is64;
    if (threadIdx.x == 0) {
        const unsigned int* w = (const unsigned int*)ei;
        unsigned int acc = 0;
#pragma unroll
        for (int k = 0; k < 8; k++) acc |= w[2 * k + 1];
        s_is64 = (acc == 0u) ? 1 : 0;
    }
    __syncthreads();

    const int tid = blockIdx.x * blockDim.x + threadIdx.x;
    const long long base = (long long)tid * EPT;
    if (base >= N_EDGES) return;

    int r[EPT], c[EPT];
    if (s_is64) {
        const longlong2* row = (const longlong2*)ei;          // edge_index[0]
        const longlong2* col = row + (N_EDGES / 2);           // edge_index[1]
        longlong2 r0 = __ldg(&row[base / 2]);
        longlong2 r1 = __ldg(&row[base / 2 + 1]);
        longlong2 c0 = __ldg(&col[base / 2]);
        longlong2 c1 = __ldg(&col[base / 2 + 1]);
        r[0] = (int)r0.x; r[1] = (int)r0.y; r[2] = (int)r1.x; r[3] = (int)r1.y;
        c[0] = (int)c0.x; c[1] = (int)c0.y; c[2] = (int)c1.x; c[3] = (int)c1.y;
    } else {
        const int4* row = (const int4*)ei;
        const int4* col = row + (N_EDGES / 4);
        int4 rv = __ldg(&row[base / 4]);
        int4 cv = __ldg(&col[base / 4]);
        r[0] = rv.x; r[1] = rv.y; r[2] = rv.z; r[3] = rv.w;
        c[0] = cv.x; c[1] = cv.y; c[2] = cv.z; c[3] = cv.w;
    }

    float v[EPT];
#pragma unroll
    for (int k = 0; k < EPT; k++) v[k] = __ldg(&x[c[k]]);
#pragma unroll
    for (int k = 0; k < EPT; k++) atomicAdd(&g_acc[r[k]], v[k]);
}

// ---------------------------------------------------------------------------
// Node phase: 2->16->16 MLP, ONE thread per node.
//  - x[n] and g_acc[n] loads issued BEFORE the weight barrier (independent of
//    smem) so their latency hides under the barrier wait.
//  - Same thread reads g_acc[n] then stores 0 back: no inter-thread hazard,
//    no mid-kernel barrier (R6's 16.9us regression came from that barrier).
//  - Layer 2 weights read as LDS.128 (64 per node vs 256 scalar in R3).
// ---------------------------------------------------------------------------
__global__ void __launch_bounds__(256) node_kernel(const float* __restrict__ x,
                                                   const float* __restrict__ w1,
                                                   const float* __restrict__ b1,
                                                   const float* __restrict__ w2,
                                                   const float* __restrict__ b2,
                                                   float* __restrict__ out) {
    __shared__ float sw1[2 * TD];
    __shared__ float sb1[TD];
    __shared__ __align__(16) float sw2[TD * TD];
    __shared__ float sb2[TD];

    const int t = threadIdx.x;
    const int n = blockIdx.x * 256 + t;
    const bool act = (n < N_NODES);

    // Issue global loads first — latency overlaps the weight staging + barrier.
    float s = 0.f, lfa = 0.f;
    if (act) { s = x[n]; lfa = g_acc[n]; }

    if (t < 2 * TD) sw1[t] = w1[t];
    if (t < TD) { sb1[t] = b1[t]; sb2[t] = b2[t]; }
    sw2[t] = w2[t];   // blockDim == 256 == TD*TD
    __syncthreads();

    // Clear for next replay: same thread, same address -> ordered after read.
    if (act) g_acc[n] = 0.0f;

    const float lf = s * lfa;

    // Layer 1: h = relu(s*w1[:,0] + lf*w1[:,1] + b1)   (broadcast LDS)
    float h[TD];
#pragma unroll
    for (int j = 0; j < TD; j++) {
        float v = fmaf(sw1[2 * j + 1], lf, fmaf(sw1[2 * j], s, sb1[j]));
        h[j] = v > 0.f ? v : 0.f;
    }

    // Layer 2: 16 outputs, weights via LDS.128 (broadcast, conflict-free).
    float4* o = (float4*)(out + (size_t)n * TD);
#pragma unroll
    for (int k4 = 0; k4 < 4; k4++) {
        float4 res;
        float* rp = (float*)&res;
#pragma unroll
        for (int kk = 0; kk < 4; kk++) {
            const int k = k4 * 4 + kk;
            float v = sb2[k];
            const float4* wrow = (const float4*)&sw2[k * TD];
#pragma unroll
            for (int j4 = 0; j4 < 4; j4++) {
                float4 w = wrow[j4];
                v = fmaf(w.x, h[j4 * 4 + 0], v);
                v = fmaf(w.y, h[j4 * 4 + 1], v);
                v = fmaf(w.z, h[j4 * 4 + 2], v);
                v = fmaf(w.w, h[j4 * 4 + 3], v);
            }
            rp[kk] = v > 0.f ? v : 0.f;
        }
        if (act) o[k4] = res;
    }
}

extern "C" void kernel_launch(void* const* d_in, const int* in_sizes, int n_in,
                              void* d_out, int out_size) {
    const float* x  = (const float*)d_in[0];
    const void*  ei = d_in[1];
    const float* w1 = (const float*)d_in[2];
    const float* b1 = (const float*)d_in[3];
    const float* w2 = (const float*)d_in[4];
    const float* b2 = (const float*)d_in[5];
    float* out = (float*)d_out;

    edge_kernel<<<N_EDGES / EPT / 256, 256>>>(ei, x);
    node_kernel<<<(N_NODES + 255) / 256, 256>>>(x, w1, b1, w2, b2, out);
}